// round 1
// baseline (speedup 1.0000x reference)
#include <cuda_runtime.h>
#include <cstdint>
#include <cstddef>

#define Hdim 1024
#define Edim 18432
#define Vdim 32000
#define Bdim 256
#define Tlen 15

struct State {
    float feat[Hdim];
    float h[Hdim], c[Hdim];
    float tmph[Hdim], tmpc[Hdim];
    float h1[2][Hdim], c1[2][Hdim];
    float h2[2][Hdim], c2[2][Hdim];
    float h3[2][Hdim], c3[2][Hdim];
    float word[Hdim];
    unsigned long long amax;
};
__device__ State g_s;

__device__ __forceinline__ float sigf(float x) { return 1.0f / (1.0f + expf(-x)); }

__device__ __forceinline__ float warp_sum(float s) {
#pragma unroll
    for (int o = 16; o; o >>= 1) s += __shfl_xor_sync(0xffffffffu, s, o);
    return s;
}

// block reduce across 256 threads (8 warps)
__device__ __forceinline__ float block_sum(float s) {
    __shared__ float sm[8];
    __shared__ float outv;
    int w = threadIdx.x >> 5, lane = threadIdx.x & 31;
    s = warp_sum(s);
    if (lane == 0) sm[w] = s;
    __syncthreads();
    if (w == 0) {
        float r = (lane < 8) ? sm[lane] : 0.0f;
        r = warp_sum(r);
        if (lane == 0) outv = r;
    }
    __syncthreads();
    float res = outv;
    __syncthreads();   // protect sm/outv for a subsequent block_sum call
    return res;
}

// feat[j] = relu(dot(fc1_w[j,:], features_row0) + fc1_b[j]); also resets argmax slot
__global__ void k_fc1(const float* __restrict__ feats, const float* __restrict__ w,
                      const float* __restrict__ bias) {
    int j = blockIdx.x;
    const float4* Wr = (const float4*)(w + (size_t)j * Edim);
    const float4* x  = (const float4*)feats;
    float s = 0.0f;
    for (int i = threadIdx.x; i < Edim / 4; i += 256) {
        float4 a = Wr[i], v = x[i];
        s += a.x * v.x + a.y * v.y + a.z * v.z + a.w * v.w;
    }
    s = block_sum(s);
    if (threadIdx.x == 0) {
        g_s.feat[j] = fmaxf(s + bias[j], 0.0f);
        if (j == 0) g_s.amax = 0ull;
    }
}

// hpre/cpre = relu(init_{h,c}_w @ feat + b)   (2048 blocks: first 1024 -> h, rest -> c)
__global__ void k_init(const float* __restrict__ wh, const float* __restrict__ bh,
                       const float* __restrict__ wc, const float* __restrict__ bc) {
    int j = blockIdx.x;
    bool is_h = (j < Hdim);
    int r = is_h ? j : j - Hdim;
    const float* w = is_h ? wh : wc;
    const float4* Wr = (const float4*)(w + (size_t)r * Hdim);
    const float4* x  = (const float4*)g_s.feat;
    float4 a = Wr[threadIdx.x], v = x[threadIdx.x];
    float s = a.x * v.x + a.y * v.y + a.z * v.z + a.w * v.w;
    s = block_sum(s);
    if (threadIdx.x == 0) {
        float val = fmaxf(s + (is_h ? bh[r] : bc[r]), 0.0f);
        if (is_h) g_s.tmph[r] = val; else g_s.tmpc[r] = val;
    }
}

// out = LN(x)*g + b (+ base if non-null). grid = 2 (block 0: set0, block 1: set1)
__global__ void k_ln(const float* x0, const float* g0, const float* b0, const float* base0, float* o0,
                     const float* x1, const float* g1, const float* b1, const float* base1, float* o1) {
    const float* x    = blockIdx.x ? x1 : x0;
    const float* g    = blockIdx.x ? g1 : g0;
    const float* b    = blockIdx.x ? b1 : b0;
    const float* base = blockIdx.x ? base1 : base0;
    float* o          = blockIdx.x ? o1 : o0;
    float xv[4];
    float s = 0.0f;
#pragma unroll
    for (int k = 0; k < 4; k++) { xv[k] = x[threadIdx.x + 256 * k]; s += xv[k]; }
    float m = block_sum(s) * (1.0f / Hdim);
    float q = 0.0f;
#pragma unroll
    for (int k = 0; k < 4; k++) { float d = xv[k] - m; q += d * d; }
    float v = block_sum(q) * (1.0f / Hdim);
    float inv = rsqrtf(v + 1e-5f);
#pragma unroll
    for (int k = 0; k < 4; k++) {
        int i = threadIdx.x + 256 * k;
        float r = (xv[k] - m) * inv * g[i] + b[i];
        if (base) r += base[i];
        o[i] = r;
    }
}

// Fused LSTM cell: block j computes gates i,f,g,o for hidden element j (warp-per-row GEMV)
// then does the pointwise update. Gate order (torch LSTMCell): i, f, g, o.
__global__ void k_cell(const float* __restrict__ x, const float* __restrict__ hin,
                       const float* __restrict__ cin,
                       const float* __restrict__ wih, const float* __restrict__ whh,
                       const float* __restrict__ bih, const float* __restrict__ bhh,
                       float* __restrict__ hout, float* __restrict__ cout) {
    int j = blockIdx.x;
    int w = threadIdx.x >> 5, lane = threadIdx.x & 31;
    const float* Wm  = (w < 4) ? wih : whh;
    const float* vec = (w < 4) ? x : hin;
    int row = j + (w & 3) * Hdim;
    const float4* Wr = (const float4*)(Wm + (size_t)row * Hdim);
    const float4* v4 = (const float4*)vec;
    float s = 0.0f;
#pragma unroll
    for (int i = 0; i < 8; i++) {
        float4 a = Wr[lane + 32 * i], b = v4[lane + 32 * i];
        s += a.x * b.x + a.y * b.y + a.z * b.z + a.w * b.w;
    }
    s = warp_sum(s);
    __shared__ float red[8];
    if (lane == 0) red[w] = s;
    __syncthreads();
    if (threadIdx.x == 0) {
        float gi = red[0] + red[4] + bih[j]            + bhh[j];
        float gf = red[1] + red[5] + bih[j + Hdim]     + bhh[j + Hdim];
        float gg = red[2] + red[6] + bih[j + 2 * Hdim] + bhh[j + 2 * Hdim];
        float go = red[3] + red[7] + bih[j + 3 * Hdim] + bhh[j + 3 * Hdim];
        float cn = sigf(gf) * cin[j] + sigf(gi) * tanhf(gg);
        float hn = sigf(go) * tanhf(cn);
        cout[j] = cn;
        hout[j] = hn;
    }
}

// pred = fc_w @ h3 + fc_b, fused argmax. Warp handles 4 rows; 1 atomicMax per block.
// Packed key: ordered-float in high 32 bits, (0xFFFFFFFF - idx) in low -> lowest idx wins ties.
__global__ void k_fc(const float* __restrict__ h3, const float* __restrict__ w,
                     const float* __restrict__ bias) {
    int warp = threadIdx.x >> 5, lane = threadIdx.x & 31;
    int r0 = (blockIdx.x * 8 + warp) * 4;
    const float4* x = (const float4*)h3;
    float acc[4] = {0.f, 0.f, 0.f, 0.f};
#pragma unroll
    for (int i = 0; i < 8; i++) {
        float4 xv = x[lane + 32 * i];
#pragma unroll
        for (int rr = 0; rr < 4; rr++) {
            const float4* Wr = (const float4*)(w + (size_t)(r0 + rr) * Hdim);
            float4 a = Wr[lane + 32 * i];
            acc[rr] += a.x * xv.x + a.y * xv.y + a.z * xv.z + a.w * xv.w;
        }
    }
    unsigned long long best = 0ull;
#pragma unroll
    for (int rr = 0; rr < 4; rr++) {
        float s = warp_sum(acc[rr]);
        if (lane == 0) {
            float val = s + bias[r0 + rr];
            unsigned u = __float_as_uint(val);
            u = (u & 0x80000000u) ? ~u : (u | 0x80000000u);
            unsigned long long p = ((unsigned long long)u << 32) |
                                   (unsigned long long)(0xFFFFFFFFu - (unsigned)(r0 + rr));
            if (p > best) best = p;
        }
    }
    __shared__ unsigned long long sb[8];
    if (lane == 0) sb[warp] = best;
    __syncthreads();
    if (threadIdx.x == 0) {
        unsigned long long m = sb[0];
#pragma unroll
        for (int k = 1; k < 8; k++) if (sb[k] > m) m = sb[k];
        atomicMax(&g_s.amax, m);
    }
}

// read argmax -> write out column t (scalar broadcast over batch), gather embedding row, reset slot
__global__ void k_finish(const float* __restrict__ embed, const float* __restrict__ tot,
                         float* __restrict__ out, int t) {
    __shared__ int sidx;
    if (threadIdx.x == 0) {
        unsigned long long p = g_s.amax;
        sidx = (int)(0xFFFFFFFFu - (unsigned)(p & 0xFFFFFFFFull));
        g_s.amax = 0ull;
    }
    __syncthreads();
    int idx = sidx;
    const float* er = embed + (size_t)idx * Hdim;
#pragma unroll
    for (int k = 0; k < 4; k++) g_s.word[threadIdx.x + 256 * k] = er[threadIdx.x + 256 * k];
    float val = tot[idx];
    out[threadIdx.x * Tlen + t] = val;   // blockDim == Bdim == 256
}

extern "C" void kernel_launch(void* const* d_in, const int* in_sizes, int n_in,
                              void* d_out, int out_size) {
    const float* features  = (const float*)d_in[0];
    const float* fc1_w     = (const float*)d_in[1];
    const float* fc1_b     = (const float*)d_in[2];
    const float* init_h_w  = (const float*)d_in[3];
    const float* init_h_b  = (const float*)d_in[4];
    const float* init_c_w  = (const float*)d_in[5];
    const float* init_c_b  = (const float*)d_in[6];
    const float* ln_h_g    = (const float*)d_in[7];
    const float* ln_h_b    = (const float*)d_in[8];
    const float* ln_c_g    = (const float*)d_in[9];
    const float* ln_c_b    = (const float*)d_in[10];
    const float* w_ih1     = (const float*)d_in[11];
    const float* w_hh1     = (const float*)d_in[12];
    const float* b_ih1     = (const float*)d_in[13];
    const float* b_hh1     = (const float*)d_in[14];
    const float* w_ih2     = (const float*)d_in[15];
    const float* w_hh2     = (const float*)d_in[16];
    const float* b_ih2     = (const float*)d_in[17];
    const float* b_hh2     = (const float*)d_in[18];
    const float* fc_w      = (const float*)d_in[19];
    const float* fc_b      = (const float*)d_in[20];
    const float* embed_w   = (const float*)d_in[21];
    const float* totoken_w = (const float*)d_in[22];
    float* out = (float*)d_out;

    State* S = nullptr;
    cudaGetSymbolAddress((void**)&S, g_s);

    // ---- prologue (t = 0) ----
    k_fc1<<<Hdim, 256>>>(features, fc1_w, fc1_b);
    k_init<<<2 * Hdim, 256>>>(init_h_w, init_h_b, init_c_w, init_c_b);
    k_ln<<<2, 256>>>(S->tmph, ln_h_g, ln_h_b, nullptr, S->h,
                     S->tmpc, ln_c_g, ln_c_b, nullptr, S->c);
    k_cell<<<Hdim, 256>>>(S->feat,  S->h, S->c, w_ih1, w_hh1, b_ih1, b_hh1, S->h1[0], S->c1[0]);
    k_cell<<<Hdim, 256>>>(S->h1[0], S->h, S->c, w_ih2, w_hh2, b_ih2, b_hh2, S->h2[0], S->c2[0]);
    k_cell<<<Hdim, 256>>>(S->h2[0], S->h, S->c, w_ih2, w_hh2, b_ih2, b_hh2, S->h3[0], S->c3[0]);
    k_fc<<<Vdim / 32, 256>>>(S->h3[0], fc_w, fc_b);
    k_finish<<<1, 256>>>(embed_w, totoken_w, out, 0);

    // ---- decode loop (t = 1 .. 14), ping-pong state buffers ----
    int p = 0;
    for (int t = 1; t < Tlen; t++) {
        int q = 1 - p;
        k_ln<<<2, 256>>>(S->h1[p], ln_h_g, ln_h_b, S->h, S->tmph,
                         S->c1[p], ln_c_g, ln_c_b, S->c, S->tmpc);
        k_cell<<<Hdim, 256>>>(S->word,  S->tmph,  S->tmpc,  w_ih1, w_hh1, b_ih1, b_hh1, S->h1[q], S->c1[q]);
        k_cell<<<Hdim, 256>>>(S->h1[q], S->h2[p], S->c2[p], w_ih2, w_hh2, b_ih2, b_hh2, S->h2[q], S->c2[q]);
        k_cell<<<Hdim, 256>>>(S->h2[q], S->h3[p], S->c3[p], w_ih2, w_hh2, b_ih2, b_hh2, S->h3[q], S->c3[q]);
        k_fc<<<Vdim / 32, 256>>>(S->h3[q], fc_w, fc_b);
        k_finish<<<1, 256>>>(embed_w, totoken_w, out, t);
        p = q;
    }
}